// round 2
// baseline (speedup 1.0000x reference)
#include <cuda_runtime.h>

#define HN 4096

static __device__ __constant__ float EPf = 1e-20f;

constexpr int TH = 64;                 // output rows per tile
constexpr int ITERS = TH + 8;          // warmup rows included (multiple of 4)
constexpr int OUTW = 112;              // valid output cols per warp strip
constexpr int NSTRIPS = (HN + OUTW - 1) / OUTW;   // 37
constexpr int WPB = 4;                 // warps per block
constexpr int GRIDX = (NSTRIPS + WPB - 1) / WPB;  // 10
constexpr int GRIDY = HN / TH;         // 64

__device__ double g_acc;

__global__ void zero_acc_kernel() { g_acc = 0.0; }

__global__ void finalize_kernel(float* out) {
    double m = g_acc * (1.0 / ((double)HN * (double)HN));
    out[0] = (float)m;
    out[1] = (float)m;
}

__device__ __forceinline__ float4 ld4(const float* p, bool v) {
    float4 r = make_float4(0.f, 0.f, 0.f, 0.f);
    if (v) r = *reinterpret_cast<const float4*>(p);
    return r;
}

__device__ __forceinline__ float4 sum4(const float4* a) {
    float4 r;
    r.x = a[0].x + a[1].x + a[2].x + a[3].x;
    r.y = a[0].y + a[1].y + a[2].y + a[3].y;
    r.z = a[0].z + a[1].z + a[2].z + a[3].z;
    r.w = a[0].w + a[1].w + a[2].w + a[3].w;
    return r;
}

// Horizontal window sum G[c] = v[c-1]+v[c]+v[c+1]+v[c+2] for this lane's 4 cols.
// vl = left neighbor's .w, vr0/vr1 = right neighbor's .x/.y
__device__ __forceinline__ float4 hwin(float4 v, float vl, float vr0, float vr1) {
    float4 g;
    g.x = vl + v.x + v.y + v.z;
    g.y = g.x - vl + v.w;
    g.z = g.y - v.x + vr0;
    g.w = g.z - v.y + vr1;
    return g;
}

__global__ void __launch_bounds__(WPB * 32)
xcorr_kernel(const float* __restrict__ X, const float* __restrict__ Y) {
    const int lane = threadIdx.x & 31;
    const int warp = threadIdx.x >> 5;
    const int strip = blockIdx.x * WPB + warp;        // may exceed NSTRIPS-1: fully masked
    const int ty0 = blockIdx.y * TH;
    const long col0 = (long)strip * OUTW - 8 + 4 * lane;

    const bool ld_ok = (col0 >= 0) && (col0 + 3 < HN);

    float m_c1[4], m_out[4];
#pragma unroll
    for (int k = 0; k < 4; ++k) {
        long c = col0 + k;
        bool inimg = (c >= 0) && (c < HN);
        m_c1[k]  = (lane >= 1 && lane <= 30 && inimg) ? 1.f : 0.f;
        m_out[k] = (lane >= 2 && lane <= 29 && inimg) ? 1.f : 0.f;
    }

    const int i0 = ty0 - 8;   // i0 % 4 == 0  (TH=64)

    // running pointers for prefetch loads of row (i + 6)
    const float* pX = X + col0 + (long)(i0 + 6) * HN;
    const float* pY = Y + col0 + (long)(i0 + 6) * HN;

    // preload rows i0+4, i0+5
    bool v4 = ld_ok && (i0 + 4) >= 0 && (i0 + 4) < HN;
    bool v5 = ld_ok && (i0 + 5) >= 0 && (i0 + 5) < HN;
    float4 xb0 = ld4(X + col0 + (long)(i0 + 4) * HN, v4);
    float4 yb0 = ld4(Y + col0 + (long)(i0 + 4) * HN, v4);
    float4 xb1 = ld4(X + col0 + (long)(i0 + 5) * HN, v5);
    float4 yb1 = ld4(Y + col0 + (long)(i0 + 5) * HN, v5);

    // ring buffers (slot = row & 3; i0 multiple of 4 keeps indices static under unroll)
    float4 xr[4], yr[4];          // raw rows
    float4 hx[4], hy[4];          // horizontal sums of x,y
    float4 hii[4], hjj[4], hij[4];// horizontal sums of products
#pragma unroll
    for (int s = 0; s < 4; ++s) {
        float4 z = make_float4(0.f, 0.f, 0.f, 0.f);
        xr[s] = z; yr[s] = z; hx[s] = z; hy[s] = z;
        hii[s] = z; hjj[s] = z; hij[s] = z;
    }

    float acc = 0.f;

#define STEP(T, S) do {                                                          \
    const int i = i0 + (T) + (S);                                                \
    float4 xc = xb0; xb0 = xb1;                                                  \
    float4 yc = yb0; yb0 = yb1;                                                  \
    {   bool v = ld_ok && (i + 6) >= 0 && (i + 6) < HN;                          \
        xb1 = ld4(pX, v); yb1 = ld4(pY, v); pX += HN; pY += HN; }                \
    xr[(S)] = xc; yr[(S)] = yc;   /* row i+4 -> slot (i+4)&3 == S */             \
    {   float xl  = __shfl_up_sync(0xffffffffu, xc.w, 1);                        \
        float xr0 = __shfl_down_sync(0xffffffffu, xc.x, 1);                      \
        float xr1 = __shfl_down_sync(0xffffffffu, xc.y, 1);                      \
        hx[(S)] = hwin(xc, xl, xr0, xr1);                                        \
        float yl  = __shfl_up_sync(0xffffffffu, yc.w, 1);                        \
        float yr0 = __shfl_down_sync(0xffffffffu, yc.x, 1);                      \
        float yr1 = __shfl_down_sync(0xffffffffu, yc.y, 1);                      \
        hy[(S)] = hwin(yc, yl, yr0, yr1); }                                      \
    /* c1,c2 for row i+2 (slot (S+2)&3) */                                       \
    {   const int r2 = i + 2;                                                    \
        const float rowm = (r2 >= 0 && r2 < HN) ? 1.f : 0.f;                     \
        float4 x2 = xr[((S) + 2) & 3], y2 = yr[((S) + 2) & 3];                   \
        float4 mx = sum4(hx), my = sum4(hy);                                     \
        float4 c1, c2; float mk;                                                 \
        mk = m_c1[0] * rowm;                                                     \
        c1.x = (x2.x - mx.x * 0.0625f) * mk; c2.x = (y2.x - my.x * 0.0625f) * mk;\
        mk = m_c1[1] * rowm;                                                     \
        c1.y = (x2.y - mx.y * 0.0625f) * mk; c2.y = (y2.y - my.y * 0.0625f) * mk;\
        mk = m_c1[2] * rowm;                                                     \
        c1.z = (x2.z - mx.z * 0.0625f) * mk; c2.z = (y2.z - my.z * 0.0625f) * mk;\
        mk = m_c1[3] * rowm;                                                     \
        c1.w = (x2.w - mx.w * 0.0625f) * mk; c2.w = (y2.w - my.w * 0.0625f) * mk;\
        float al  = __shfl_up_sync(0xffffffffu, c1.w, 1);                        \
        float bl  = __shfl_up_sync(0xffffffffu, c2.w, 1);                        \
        float ar0 = __shfl_down_sync(0xffffffffu, c1.x, 1);                      \
        float br0 = __shfl_down_sync(0xffffffffu, c2.x, 1);                      \
        float ar1 = __shfl_down_sync(0xffffffffu, c1.y, 1);                      \
        float br1 = __shfl_down_sync(0xffffffffu, c2.y, 1);                      \
        {   float4 p; float pl = al * al, pr0 = ar0 * ar0, pr1 = ar1 * ar1;      \
            p.x = c1.x * c1.x; p.y = c1.y * c1.y;                                \
            p.z = c1.z * c1.z; p.w = c1.w * c1.w;                                \
            hii[((S) + 2) & 3] = hwin(p, pl, pr0, pr1); }                        \
        {   float4 p; float pl = bl * bl, pr0 = br0 * br0, pr1 = br1 * br1;      \
            p.x = c2.x * c2.x; p.y = c2.y * c2.y;                                \
            p.z = c2.z * c2.z; p.w = c2.w * c2.w;                                \
            hjj[((S) + 2) & 3] = hwin(p, pl, pr0, pr1); }                        \
        {   float4 p; float pl = al * bl, pr0 = ar0 * br0, pr1 = ar1 * br1;      \
            p.x = c1.x * c2.x; p.y = c1.y * c2.y;                                \
            p.z = c1.z * c2.z; p.w = c1.w * c2.w;                                \
            hij[((S) + 2) & 3] = hwin(p, pl, pr0, pr1); }                        \
    }                                                                            \
    if ((T) + (S) >= 8) {  /* output row i */                                    \
        float4 sii = sum4(hii), sjj = sum4(hjj), sij = sum4(hij);                \
        {   float a_ = fmaxf(sii.x, EPf), b_ = fmaxf(sjj.x, EPf);                \
            float L = sij.x * rsqrtf(a_ * b_); L = fmaxf(L, -1.f);               \
            acc = fmaf(1.f - L, m_out[0], acc); }                                \
        {   float a_ = fmaxf(sii.y, EPf), b_ = fmaxf(sjj.y, EPf);                \
            float L = sij.y * rsqrtf(a_ * b_); L = fmaxf(L, -1.f);               \
            acc = fmaf(1.f - L, m_out[1], acc); }                                \
        {   float a_ = fmaxf(sii.z, EPf), b_ = fmaxf(sjj.z, EPf);                \
            float L = sij.z * rsqrtf(a_ * b_); L = fmaxf(L, -1.f);               \
            acc = fmaf(1.f - L, m_out[2], acc); }                                \
        {   float a_ = fmaxf(sii.w, EPf), b_ = fmaxf(sjj.w, EPf);                \
            float L = sij.w * rsqrtf(a_ * b_); L = fmaxf(L, -1.f);               \
            acc = fmaf(1.f - L, m_out[3], acc); }                                \
    }                                                                            \
} while (0)

#pragma unroll 1
    for (int T = 0; T < ITERS; T += 4) {
        STEP(T, 0);
        STEP(T, 1);
        STEP(T, 2);
        STEP(T, 3);
    }
#undef STEP

    // reduce: warp -> block -> global double
#pragma unroll
    for (int o = 16; o; o >>= 1) acc += __shfl_xor_sync(0xffffffffu, acc, o);

    __shared__ float wsum[WPB];
    if (lane == 0) wsum[warp] = acc;
    __syncthreads();
    if (threadIdx.x == 0) {
        float s = 0.f;
#pragma unroll
        for (int w2 = 0; w2 < WPB; ++w2) s += wsum[w2];
        atomicAdd(&g_acc, (double)s);
    }
}

extern "C" void kernel_launch(void* const* d_in, const int* in_sizes, int n_in,
                              void* d_out, int out_size) {
    const float* X = (const float*)d_in[0];   // outputs
    const float* Y = (const float*)d_in[1];   // labels

    zero_acc_kernel<<<1, 1>>>();
    dim3 grid(GRIDX, GRIDY);
    xcorr_kernel<<<grid, WPB * 32>>>(X, Y);
    finalize_kernel<<<1, 1>>>((float*)d_out);
}